// round 7
// baseline (speedup 1.0000x reference)
#include <cuda_runtime.h>
#include <cstdint>

// -------------------------------------------------------------------------
// SpecialSpmmFinal: out[n,f] = sum_{e : src[e]==n} edge_w[e,f]
// N=100000, E=3200000, F=16 fp32.
//
// CSR-build + conflict-free gather (no float atomics):
//   1. count[n] = #edges with src==n            (int atomics)
//   2. offset = exclusive_scan(count)           (3 tiny kernels)
//   3. eid[offset[n] + k] = e                   (int atomics for slot)
//   4. out[n,:] = sum over eid list             (pure gather, coalesced write)
// -------------------------------------------------------------------------

#define NN   100000
#define EE   3200000
#define FEAT 16
#define SCAN_BLK 256
#define NBLK ((NN + SCAN_BLK - 1) / SCAN_BLK)   // 391

__device__ int g_count[NN];
__device__ int g_offset[NN];
__device__ int g_cursor[NN];
__device__ int g_eid[EE];
__device__ int g_blocksum[NBLK];

// ---- 1. zero counts -----------------------------------------------------
__global__ __launch_bounds__(256)
void zero_count_kernel() {
    int i = blockIdx.x * blockDim.x + threadIdx.x;
    if (i < NN) g_count[i] = 0;
}

// ---- 2. histogram -------------------------------------------------------
__global__ __launch_bounds__(256)
void count_kernel(const int* __restrict__ src, int E) {
    int e = blockIdx.x * blockDim.x + threadIdx.x;
    if (e < E) atomicAdd(&g_count[src[e]], 1);
}

// ---- 3a. per-block inclusive scan -> local exclusive + block sums -------
__global__ __launch_bounds__(SCAN_BLK)
void scan1_kernel() {
    __shared__ int s[SCAN_BLK];
    int i = blockIdx.x * SCAN_BLK + threadIdx.x;
    int v = (i < NN) ? g_count[i] : 0;
    s[threadIdx.x] = v;
    __syncthreads();
    #pragma unroll
    for (int off = 1; off < SCAN_BLK; off <<= 1) {
        int x = s[threadIdx.x] + ((threadIdx.x >= off) ? s[threadIdx.x - off] : 0);
        __syncthreads();
        s[threadIdx.x] = x;
        __syncthreads();
    }
    // exclusive value for element i = inclusive[i] - v
    if (i < NN) g_offset[i] = s[threadIdx.x] - v;
    if (threadIdx.x == SCAN_BLK - 1) g_blocksum[blockIdx.x] = s[SCAN_BLK - 1];
}

// ---- 3b. scan the 391 block sums (single block) -------------------------
__global__ __launch_bounds__(512)
void scan2_kernel() {
    __shared__ int s[512];
    int i = threadIdx.x;
    int v = (i < NBLK) ? g_blocksum[i] : 0;
    s[i] = v;
    __syncthreads();
    #pragma unroll
    for (int off = 1; off < 512; off <<= 1) {
        int x = s[i] + ((i >= off) ? s[i - off] : 0);
        __syncthreads();
        s[i] = x;
        __syncthreads();
    }
    if (i < NBLK) g_blocksum[i] = s[i] - v;   // exclusive
}

// ---- 3c. add block offsets, init cursors --------------------------------
__global__ __launch_bounds__(SCAN_BLK)
void scan3_kernel() {
    int i = blockIdx.x * SCAN_BLK + threadIdx.x;
    if (i < NN) {
        int o = g_offset[i] + g_blocksum[blockIdx.x];
        g_offset[i] = o;
        g_cursor[i] = o;
    }
}

// ---- 4. fill edge id lists ----------------------------------------------
__global__ __launch_bounds__(256)
void fill_kernel(const int* __restrict__ src, int E) {
    int e = blockIdx.x * blockDim.x + threadIdx.x;
    if (e < E) {
        int pos = atomicAdd(&g_cursor[src[e]], 1);
        g_eid[pos] = e;
    }
}

// ---- 5. gather: 16 threads per node, lane = feature ---------------------
__global__ __launch_bounds__(256)
void gather_kernel(const float* __restrict__ w,   // [E,16]
                   float* __restrict__ out,       // [N,16]
                   int N) {
    int tid   = threadIdx.x;
    int f     = tid & 15;
    int group = tid >> 4;                   // 16 groups per block
    int n     = blockIdx.x * 16 + group;
    if (n >= N) return;

    int start = g_offset[n];
    int cnt   = g_count[n];

    float a0 = 0.f, a1 = 0.f, a2 = 0.f, a3 = 0.f;
    int j = 0;
    // Unroll x4: 4 independent eid loads + 4 independent edge_w loads in flight.
    for (; j + 4 <= cnt; j += 4) {
        int e0 = g_eid[start + j + 0];
        int e1 = g_eid[start + j + 1];
        int e2 = g_eid[start + j + 2];
        int e3 = g_eid[start + j + 3];
        a0 += __ldg(&w[(size_t)e0 * FEAT + f]);
        a1 += __ldg(&w[(size_t)e1 * FEAT + f]);
        a2 += __ldg(&w[(size_t)e2 * FEAT + f]);
        a3 += __ldg(&w[(size_t)e3 * FEAT + f]);
    }
    for (; j < cnt; j++) {
        int e0 = g_eid[start + j];
        a0 += __ldg(&w[(size_t)e0 * FEAT + f]);
    }
    out[(size_t)n * FEAT + f] = (a0 + a1) + (a2 + a3);
}

extern "C" void kernel_launch(void* const* d_in, const int* in_sizes, int n_in,
                              void* d_out, int out_size) {
    const int*   edge   = (const int*)d_in[0];    // [2,E], row 0 = src
    const float* edge_w = (const float*)d_in[1];  // [E,16]
    float*       out    = (float*)d_out;          // [N,16]

    const int E = in_sizes[0] / 2;
    const int N = out_size / FEAT;

    int eblk = (E + 255) / 256;

    zero_count_kernel<<<NBLK, 256>>>();
    count_kernel<<<eblk, 256>>>(edge, E);
    scan1_kernel<<<NBLK, SCAN_BLK>>>();
    scan2_kernel<<<1, 512>>>();
    scan3_kernel<<<NBLK, SCAN_BLK>>>();
    fill_kernel<<<eblk, 256>>>(edge, E);
    gather_kernel<<<(N + 15) / 16, 256>>>(edge_w, out, N);
}

// round 8
// speedup vs baseline: 2.4991x; 2.4991x over previous
#include <cuda_runtime.h>
#include <cstdint>

// -------------------------------------------------------------------------
// SpecialSpmmFinal: out[n,f] = sum_{e : src[e]==n} edge_w[e,f]
// N=100000, E=3200000, F=16 fp32.
//
// Scatter with coalesced atomics: 4 threads per edge, each owning a 16B
// quarter of the 64B feature row. Adjacent lanes target contiguous output
// bytes, so the warp's RED.128 coalesces into sector-contiguous L2 atomic
// transactions (vs 32 scattered 16B targets in the 1-thread-per-edge form).
// -------------------------------------------------------------------------

#define FEAT 16

__global__ __launch_bounds__(256)
void zero_out_kernel(float4* __restrict__ out, int n4) {
    int i = blockIdx.x * blockDim.x + threadIdx.x;
    if (i < n4) out[i] = make_float4(0.f, 0.f, 0.f, 0.f);
}

__global__ __launch_bounds__(256)
void spmm_scatter_q_kernel(const int* __restrict__ src,
                           const float4* __restrict__ w,   // [E*4] float4
                           float* __restrict__ out,        // [N*16]
                           int E) {
    int gid = blockIdx.x * blockDim.x + threadIdx.x;
    int e = gid >> 2;           // edge index
    if (e >= E) return;
    int q = gid & 3;            // quarter-row index (0..3)

    int s = __ldg(&src[e]);     // broadcast across the 4 lanes of this edge

    float4 v = __ldg(&w[(size_t)e * 4 + q]);   // warp: 8 rows x 64B contiguous

    float* o = out + (size_t)s * FEAT + q * 4; // 4 lanes -> contiguous 64B row

    asm volatile("red.global.add.v4.f32 [%0], {%1,%2,%3,%4};"
                 :: "l"(o), "f"(v.x), "f"(v.y), "f"(v.z), "f"(v.w) : "memory");
}

extern "C" void kernel_launch(void* const* d_in, const int* in_sizes, int n_in,
                              void* d_out, int out_size) {
    const int*    edge   = (const int*)d_in[0];      // [2, E], row 0 = src
    const float4* edge_w = (const float4*)d_in[1];   // [E, 16] fp32 as float4
    float*        out    = (float*)d_out;            // [N, 16] fp32

    const int E = in_sizes[0] / 2;

    // Zero the poisoned output.
    {
        int n4 = out_size / 4;
        int blocks = (n4 + 255) / 256;
        zero_out_kernel<<<blocks, 256>>>((float4*)out, n4);
    }

    // Coalesced-atomic scatter: 4 threads per edge.
    {
        long long total = (long long)E * 4;
        int blocks = (int)((total + 255) / 256);
        spmm_scatter_q_kernel<<<blocks, 256>>>(edge, edge_w, out, E);
    }
}

// round 9
// speedup vs baseline: 2.5806x; 1.0326x over previous
#include <cuda_runtime.h>
#include <cstdint>

// -------------------------------------------------------------------------
// SpecialSpmmFinal: out[n,f] = sum_{e : src[e]==n} edge_w[e,f]
// N=100000, E=3200000, F=16 fp32.
//
// Coalesced-atomic scatter (4 threads per edge own 16B quarter-rows) with
// x4 ILP: each thread processes 4 quarter-rows strided by the grid size,
// batching 8 independent loads before the 4 REDs so the long-scoreboard
// latency of the load->atomic chain is hidden by MLP instead of occupancy.
// -------------------------------------------------------------------------

#define FEAT 16
#define UNROLL 4

__global__ __launch_bounds__(256)
void zero_out_kernel(float4* __restrict__ out, int n4) {
    int i = blockIdx.x * blockDim.x + threadIdx.x;
    if (i < n4) out[i] = make_float4(0.f, 0.f, 0.f, 0.f);
}

__global__ __launch_bounds__(256)
void spmm_scatter_q4_kernel(const int* __restrict__ src,
                            const float4* __restrict__ w,   // [E*4] float4
                            float* __restrict__ out,        // [N*16]
                            int total)                      // = E*4 quarter-rows
{
    const int stride = gridDim.x * blockDim.x;
    int i = blockIdx.x * blockDim.x + threadIdx.x;

    int   idx[UNROLL];
    bool  ok [UNROLL];
    int   s  [UNROLL];
    float4 v [UNROLL];

    // Batch 1: indices + src loads (broadcast within each 4-lane group).
    #pragma unroll
    for (int k = 0; k < UNROLL; k++) {
        idx[k] = i + k * stride;
        ok[k]  = idx[k] < total;
        s[k]   = ok[k] ? __ldg(&src[idx[k] >> 2]) : 0;
    }

    // Batch 2: edge_w quarter-row loads — warp covers 8 consecutive full
    // 64B rows (512B contiguous) per k; 4 independent LDG.128 in flight.
    #pragma unroll
    for (int k = 0; k < UNROLL; k++) {
        v[k] = ok[k] ? __ldg(&w[idx[k]]) : make_float4(0.f, 0.f, 0.f, 0.f);
    }

    // Batch 3: coalesced vector reductions — 4 adjacent lanes hit one
    // contiguous 64B output row.
    #pragma unroll
    for (int k = 0; k < UNROLL; k++) {
        if (ok[k]) {
            float* o = out + (size_t)s[k] * FEAT + (idx[k] & 3) * 4;
            asm volatile("red.global.add.v4.f32 [%0], {%1,%2,%3,%4};"
                         :: "l"(o), "f"(v[k].x), "f"(v[k].y),
                            "f"(v[k].z), "f"(v[k].w) : "memory");
        }
    }
}

extern "C" void kernel_launch(void* const* d_in, const int* in_sizes, int n_in,
                              void* d_out, int out_size) {
    const int*    edge   = (const int*)d_in[0];      // [2, E], row 0 = src
    const float4* edge_w = (const float4*)d_in[1];   // [E, 16] fp32 as float4
    float*        out    = (float*)d_out;            // [N, 16] fp32

    const int E = in_sizes[0] / 2;

    // Zero the poisoned output.
    {
        int n4 = out_size / 4;
        int blocks = (n4 + 255) / 256;
        zero_out_kernel<<<blocks, 256>>>((float4*)out, n4);
    }

    // Scatter: total quarter-rows = 4E, each thread handles UNROLL of them.
    {
        long long total   = (long long)E * 4;
        long long threads = (total + UNROLL - 1) / UNROLL;
        int blocks = (int)((threads + 255) / 256);
        spmm_scatter_q4_kernel<<<blocks, 256>>>(edge, edge_w, out, (int)total);
    }
}

// round 10
// speedup vs baseline: 2.5944x; 1.0054x over previous
#include <cuda_runtime.h>
#include <cstdint>

// -------------------------------------------------------------------------
// SpecialSpmmFinal: out[n,f] = sum_{e : src[e]==n} edge_w[e,f]
// N=100000, E=3200000, F=16 fp32.
//
// Coalesced-atomic scatter, 4 threads per edge (16B quarter-rows), x8 ILP.
// - edge_w read with L1::no_allocate (streamed once; keeps L1TEX tag/data
//   bandwidth for the RED wavefronts, the binding pipe per ncu).
// - Exact-grid specialization: 12.8M quarter-rows = 6250 blocks x 256 thr
//   x 8 elems, no predication at all.
// - Output zeroed via cudaMemsetAsync (graph-capturable, cheaper than a
//   dedicated kernel launch).
// -------------------------------------------------------------------------

#define FEAT 16
#define UNROLL 8

__device__ __forceinline__ float4 ldg_stream(const float4* p) {
    float4 v;
    asm volatile("ld.global.nc.L1::no_allocate.v4.f32 {%0,%1,%2,%3}, [%4];"
                 : "=f"(v.x), "=f"(v.y), "=f"(v.z), "=f"(v.w) : "l"(p));
    return v;
}

__device__ __forceinline__ void red_v4(float* o, float4 v) {
    asm volatile("red.global.add.v4.f32 [%0], {%1,%2,%3,%4};"
                 :: "l"(o), "f"(v.x), "f"(v.y), "f"(v.z), "f"(v.w) : "memory");
}

// Exact version: total quarter-rows == gridDim.x * blockDim.x * UNROLL.
__global__ __launch_bounds__(256)
void spmm_scatter_exact_kernel(const int* __restrict__ src,
                               const float4* __restrict__ w,   // [E*4]
                               float* __restrict__ out)        // [N*16]
{
    const int stride = gridDim.x * blockDim.x;
    const int base = blockIdx.x * blockDim.x + threadIdx.x;

    int    s[UNROLL];
    float4 v[UNROLL];

    // Batch 1: src loads (broadcast within each 4-lane group).
    #pragma unroll
    for (int k = 0; k < UNROLL; k++) {
        int idx = base + k * stride;
        s[k] = __ldg(&src[idx >> 2]);
    }

    // Batch 2: streaming edge_w loads — warp covers 512B contiguous per k,
    // 8 independent LDG.128 in flight, no L1 allocation.
    #pragma unroll
    for (int k = 0; k < UNROLL; k++) {
        v[k] = ldg_stream(&w[base + k * stride]);
    }

    // Batch 3: coalesced vector reductions — 4 adjacent lanes hit one
    // contiguous 64B output row.
    #pragma unroll
    for (int k = 0; k < UNROLL; k++) {
        int idx = base + k * stride;
        red_v4(out + (size_t)s[k] * FEAT + (idx & 3) * 4, v[k]);
    }
}

// Generic fallback (predicated) for any E.
__global__ __launch_bounds__(256)
void spmm_scatter_gen_kernel(const int* __restrict__ src,
                             const float4* __restrict__ w,
                             float* __restrict__ out,
                             int total)
{
    const int stride = gridDim.x * blockDim.x;
    const int base = blockIdx.x * blockDim.x + threadIdx.x;

    #pragma unroll
    for (int k = 0; k < UNROLL; k++) {
        int idx = base + k * stride;
        if (idx < total) {
            int s = __ldg(&src[idx >> 2]);
            float4 v = ldg_stream(&w[idx]);
            red_v4(out + (size_t)s * FEAT + (idx & 3) * 4, v);
        }
    }
}

extern "C" void kernel_launch(void* const* d_in, const int* in_sizes, int n_in,
                              void* d_out, int out_size) {
    const int*    edge   = (const int*)d_in[0];      // [2, E], row 0 = src
    const float4* edge_w = (const float4*)d_in[1];   // [E, 16] as float4
    float*        out    = (float*)d_out;            // [N, 16] fp32

    const int E = in_sizes[0] / 2;

    // Zero the poisoned output (stream-ordered, graph-capturable).
    cudaMemsetAsync(out, 0, (size_t)out_size * sizeof(float));

    const long long total = (long long)E * 4;        // quarter-rows
    const int per_blk = 256 * UNROLL;

    if (total % per_blk == 0) {
        int blocks = (int)(total / per_blk);         // E=3.2M -> 6250
        spmm_scatter_exact_kernel<<<blocks, 256>>>(edge, edge_w, out);
    } else {
        long long threads = (total + UNROLL - 1) / UNROLL;
        int blocks = (int)((threads + 255) / 256);
        spmm_scatter_gen_kernel<<<blocks, 256>>>(edge, edge_w, out, (int)total);
    }
}